// round 5
// baseline (speedup 1.0000x reference)
#include <cuda_runtime.h>

// 2-layer LSTM, B=2048 T=2048 H1=36 H2=1, fp32.
// R4: 2 warps/block, 4 seqs/block, grid 512 (4 blocks/SM -> 8 warps/SM).
//   warp0: gates i,f (+ L2 for t-1, + i/f of extra units 32..35)
//   warp1: gates g,o (+ all activations, h/hr writes, + g/o of extra units)
// W held in registers (81/warp-lane); h exchanged via smem float4 (4 seqs).

#define FULLMASK 0xffffffffu
#define H1C 36
#define TT 2048

__device__ __forceinline__ float2 ffma2(float2 a, float2 b, float2 c) {
    float2 d;
    asm("fma.rn.f32x2 %0, %1, %2, %3;"
        : "=l"(reinterpret_cast<unsigned long long&>(d))
        : "l"(reinterpret_cast<unsigned long long&>(a)),
          "l"(reinterpret_cast<unsigned long long&>(b)),
          "l"(reinterpret_cast<unsigned long long&>(c)));
    return d;
}
__device__ __forceinline__ float tanha(float x) {
    float y;
    asm("tanh.approx.f32 %0, %1;" : "=f"(y) : "f"(x));
    return y;
}
__device__ __forceinline__ float sigm(float x) {
    return fmaf(0.5f, tanha(0.5f * x), 0.5f);
}

struct Smem {
    float4 h[H1C];        // h per unit, 4 seqs
    float4 hr[H1C];       // relu(h)
    float2 gif[4][32];    // warp0 -> warp1: (i,f) preacts, per seq, per unit(lane)
    float4 eIF[8];        // extra units: i (0..3), f (4..7) preacts, 4 seqs
    float4 eGO[8];        // extra units: g (0..3), o (4..7) preacts, 4 seqs
};

__global__ void __launch_bounds__(64, 4)
lstm2_kernel(const float* __restrict__ x,
             const float* __restrict__ W_ih1, const float* __restrict__ W_hh1,
             const float* __restrict__ b_ih1, const float* __restrict__ b_hh1,
             const float* __restrict__ W_ih2, const float* __restrict__ W_hh2,
             const float* __restrict__ b_ih2, const float* __restrict__ b_hh2,
             float* __restrict__ out)
{
    __shared__ Smem sm;
    const int tid  = threadIdx.x;
    const int warp = tid >> 5;         // 0: i,f   1: g,o
    const int lane = tid & 31;
    const int seq0 = blockIdx.x * 4;

    // ---- register weights (direct LDG; W is tiny and L2-resident) ----
    const int rA = warp * 72 + lane;        // i-row (w0) / g-row (w1), unit=lane
    const int rB = rA + H1C;                // f-row / o-row
    float2 Wp[H1C];
    #pragma unroll
    for (int j = 0; j < H1C; ++j)
        Wp[j] = make_float2(W_hh1[rA * H1C + j], W_hh1[rB * H1C + j]);
    const float2 wihP = make_float2(W_ih1[rA], W_ih1[rB]);
    const float2 bP   = make_float2(b_ih1[rA] + b_hh1[rA], b_ih1[rB] + b_hh1[rB]);

    // extra units 32..35: slot e = lane&7 (e<4: gateA, e>=4: gateB), j-range (lane>>3)*9..+9
    const int e   = lane & 7;
    const int grp = lane >> 3;
    const int jb  = grp * 9;
    const int rE  = warp * 72 + (e >> 2) * H1C + 32 + (e & 3);
    float WE[9];
    #pragma unroll
    for (int r = 0; r < 9; ++r)
        WE[r] = W_hh1[rE * H1C + jb + r];
    const float wihE = W_ih1[rE];
    const float bE   = b_ih1[rE] + b_hh1[rE];

    // L2 weights (warp0 uses; harmless in warp1)
    const int q  = lane & 3;
    const int j0 = lane >> 2;
    float w2r[4];
    #pragma unroll
    for (int m = 0; m < 4; ++m)
        w2r[m] = W_ih2[q * H1C + j0 + 8 * m];
    const float w2x  = (j0 < 4) ? W_ih2[q * H1C + 32 + j0] : 0.0f;
    const float b2q  = b_ih2[q] + b_hh2[q];
    const float whq  = W_hh2[q];
    const float asc  = (q == 2) ? 1.0f : 0.5f;   // act = asc*tanh(asc*v)+aoc
    const float aoc  = (q == 2) ? 0.0f : 0.5f;

    if (tid < H1C) {
        sm.h[tid]  = make_float4(0.f, 0.f, 0.f, 0.f);
        sm.hr[tid] = make_float4(0.f, 0.f, 0.f, 0.f);
    }
    __syncthreads();

    const float* xb = x + (size_t)seq0 * TT;
    float* o0 = out + (size_t)seq0 * TT;
    float* o1 = o0 + TT;
    float* o2 = o1 + TT;
    float* o3 = o2 + TT;

    // states
    float c0 = 0.f, c1 = 0.f, c2 = 0.f, c3 = 0.f, cE = 0.f;            // warp1
    float l2c0 = 0.f, l2c1 = 0.f, l2c2 = 0.f, l2c3 = 0.f;               // warp0
    float l2h0 = 0.f, l2h1 = 0.f, l2h2 = 0.f, l2h3 = 0.f;
    float ob0 = 0.f, ob1 = 0.f, ob2 = 0.f, ob3 = 0.f;
    float xb0 = 0.f, xb1 = 0.f, xb2 = 0.f, xb3 = 0.f;

    // L2 pass for seq pair (a=2p, b=2p+1) at step tp; reads sm.hr (holding step-tp values)
    auto l2pass = [&](float& l2ca, float& l2ha, float& l2cb, float& l2hb,
                      float& oba, float& obb, int p, int tp,
                      float* outa, float* outb) {
        float sA = 0.f, sB = 0.f;
        #pragma unroll
        for (int m = 0; m < 4; ++m) {
            int j = j0 + 8 * m;
            float2 hh = *(const float2*)((const char*)&sm.hr[j] + p * 8);
            sA = fmaf(w2r[m], hh.x, sA);
            sB = fmaf(w2r[m], hh.y, sB);
        }
        if (j0 < 4) {
            float2 hh = *(const float2*)((const char*)&sm.hr[32 + j0] + p * 8);
            sA = fmaf(w2x, hh.x, sA);
            sB = fmaf(w2x, hh.y, sB);
        }
        #pragma unroll
        for (int off = 4; off <= 16; off <<= 1) {
            sA += __shfl_xor_sync(FULLMASK, sA, off);
            sB += __shfl_xor_sync(FULLMASK, sB, off);
        }
        float vA = sA + b2q + whq * l2ha;
        float vB = sB + b2q + whq * l2hb;
        float aAct = fmaf(asc, tanha(asc * vA), aoc);  // sigm for q!=2, tanh for q==2
        float bAct = fmaf(asc, tanha(asc * vB), aoc);
        const int base = lane & ~3;
        float iA = __shfl_sync(FULLMASK, aAct, base + 0);
        float fA = __shfl_sync(FULLMASK, aAct, base + 1);
        float gA = __shfl_sync(FULLMASK, aAct, base + 2);
        float oA = __shfl_sync(FULLMASK, aAct, base + 3);
        float iB = __shfl_sync(FULLMASK, bAct, base + 0);
        float fB = __shfl_sync(FULLMASK, bAct, base + 1);
        float gB = __shfl_sync(FULLMASK, bAct, base + 2);
        float oB = __shfl_sync(FULLMASK, bAct, base + 3);
        l2ca = fmaf(fA, l2ca, iA * gA);
        l2ha = oA * tanha(l2ca);
        l2cb = fmaf(fB, l2cb, iB * gB);
        l2hb = oB * tanha(l2cb);
        const int tmp = tp & 31;
        oba = (tmp == lane) ? l2ha : oba;
        obb = (tmp == lane) ? l2hb : obb;
        if (tmp == 31) {
            outa[tp - 31 + lane] = oba;
            outb[tp - 31 + lane] = obb;
        }
    };

    for (int t = 0; t < TT; ++t) {
        const int tm = t & 31;
        if (tm == 0) {
            xb0 = xb[t + lane];
            xb1 = xb[TT + t + lane];
            xb2 = xb[2 * TT + t + lane];
            xb3 = xb[3 * TT + t + lane];
        }
        const float x0 = __shfl_sync(FULLMASK, xb0, tm);
        const float x1 = __shfl_sync(FULLMASK, xb1, tm);
        const float x2 = __shfl_sync(FULLMASK, xb2, tm);
        const float x3 = __shfl_sync(FULLMASK, xb3, tm);

        // ---- main j-loop: acc (first half) + acc2 (second half), 4 seqs
        float2 a0 = ffma2(make_float2(x0, x0), wihP, bP);
        float2 a1 = ffma2(make_float2(x1, x1), wihP, bP);
        float2 a2 = ffma2(make_float2(x2, x2), wihP, bP);
        float2 a3 = ffma2(make_float2(x3, x3), wihP, bP);
        float2 d0 = make_float2(0.f, 0.f), d1 = d0, d2 = d0, d3 = d0;
        #pragma unroll
        for (int j = 0; j < 18; ++j) {
            float4 h4 = sm.h[j];
            a0 = ffma2(Wp[j], make_float2(h4.x, h4.x), a0);
            a1 = ffma2(Wp[j], make_float2(h4.y, h4.y), a1);
            a2 = ffma2(Wp[j], make_float2(h4.z, h4.z), a2);
            a3 = ffma2(Wp[j], make_float2(h4.w, h4.w), a3);
        }
        #pragma unroll
        for (int j = 18; j < H1C; ++j) {
            float4 h4 = sm.h[j];
            d0 = ffma2(Wp[j], make_float2(h4.x, h4.x), d0);
            d1 = ffma2(Wp[j], make_float2(h4.y, h4.y), d1);
            d2 = ffma2(Wp[j], make_float2(h4.z, h4.z), d2);
            d3 = ffma2(Wp[j], make_float2(h4.w, h4.w), d3);
        }
        a0.x += d0.x; a0.y += d0.y;
        a1.x += d1.x; a1.y += d1.y;
        a2.x += d2.x; a2.y += d2.y;
        a3.x += d3.x; a3.y += d3.y;

        // ---- extra units partials (4-lane split per slot) + reduce
        float aE0 = (grp == 0) ? fmaf(x0, wihE, bE) : 0.f;
        float aE1 = (grp == 0) ? fmaf(x1, wihE, bE) : 0.f;
        float aE2 = (grp == 0) ? fmaf(x2, wihE, bE) : 0.f;
        float aE3 = (grp == 0) ? fmaf(x3, wihE, bE) : 0.f;
        #pragma unroll
        for (int r = 0; r < 9; ++r) {
            float4 h4 = sm.h[jb + r];
            aE0 = fmaf(WE[r], h4.x, aE0);
            aE1 = fmaf(WE[r], h4.y, aE1);
            aE2 = fmaf(WE[r], h4.z, aE2);
            aE3 = fmaf(WE[r], h4.w, aE3);
        }
        aE0 += __shfl_xor_sync(FULLMASK, aE0, 8);
        aE1 += __shfl_xor_sync(FULLMASK, aE1, 8);
        aE2 += __shfl_xor_sync(FULLMASK, aE2, 8);
        aE3 += __shfl_xor_sync(FULLMASK, aE3, 8);
        aE0 += __shfl_xor_sync(FULLMASK, aE0, 16);
        aE1 += __shfl_xor_sync(FULLMASK, aE1, 16);
        aE2 += __shfl_xor_sync(FULLMASK, aE2, 16);
        aE3 += __shfl_xor_sync(FULLMASK, aE3, 16);

        if (warp == 0) {
            // L2 for previous step (reads hr(t-1): still valid pre-barrier)
            if (t) {
                l2pass(l2c0, l2h0, l2c1, l2h1, ob0, ob1, 0, t - 1, o0, o1);
                l2pass(l2c2, l2h2, l2c3, l2h3, ob2, ob3, 1, t - 1, o2, o3);
            }
            // hand off i,f preacts
            sm.gif[0][lane] = a0;
            sm.gif[1][lane] = a1;
            sm.gif[2][lane] = a2;
            sm.gif[3][lane] = a3;
            if (lane < 8) sm.eIF[lane] = make_float4(aE0, aE1, aE2, aE3);
        } else {
            if (lane < 8) sm.eGO[lane] = make_float4(aE0, aE1, aE2, aE3);
        }
        __syncthreads();   // bar1: preacts visible; hr(t-1) reads complete

        if (warp == 1) {
            // main activations: unit = lane, gates: i,f from smem; g,o = own regs
            float2 if0 = sm.gif[0][lane];
            float2 if1 = sm.gif[1][lane];
            float2 if2 = sm.gif[2][lane];
            float2 if3 = sm.gif[3][lane];
            float h0v, h1v, h2v, h3v;
            {
                float iv = sigm(if0.x), fv = sigm(if0.y), gv = tanha(a0.x), ov = sigm(a0.y);
                c0 = fmaf(fv, c0, iv * gv);  h0v = ov * tanha(c0);
            }
            {
                float iv = sigm(if1.x), fv = sigm(if1.y), gv = tanha(a1.x), ov = sigm(a1.y);
                c1 = fmaf(fv, c1, iv * gv);  h1v = ov * tanha(c1);
            }
            {
                float iv = sigm(if2.x), fv = sigm(if2.y), gv = tanha(a2.x), ov = sigm(a2.y);
                c2 = fmaf(fv, c2, iv * gv);  h2v = ov * tanha(c2);
            }
            {
                float iv = sigm(if3.x), fv = sigm(if3.y), gv = tanha(a3.x), ov = sigm(a3.y);
                c3 = fmaf(fv, c3, iv * gv);  h3v = ov * tanha(c3);
            }
            sm.h[lane]  = make_float4(h0v, h1v, h2v, h3v);
            sm.hr[lane] = make_float4(fmaxf(h0v, 0.f), fmaxf(h1v, 0.f),
                                      fmaxf(h2v, 0.f), fmaxf(h3v, 0.f));
            // extra units: lane = s*4 + u (lane < 16)
            if (lane < 16) {
                const int s = lane >> 2, u = lane & 3;
                const float iv = sigm(((const float*)&sm.eIF[u])[s]);
                const float fv = sigm(((const float*)&sm.eIF[4 + u])[s]);
                const float gv = tanha(((const float*)&sm.eGO[u])[s]);
                const float ov = sigm(((const float*)&sm.eGO[4 + u])[s]);
                cE = fmaf(fv, cE, iv * gv);
                float hv = ov * tanha(cE);
                ((float*)&sm.h[32 + u])[s]  = hv;
                ((float*)&sm.hr[32 + u])[s] = fmaxf(hv, 0.f);
            }
        }
        __syncthreads();   // bar2: h(t)/hr(t) visible to both warps
    }

    if (warp == 0) {       // final step's L2 + output flush
        l2pass(l2c0, l2h0, l2c1, l2h1, ob0, ob1, 0, TT - 1, o0, o1);
        l2pass(l2c2, l2h2, l2c3, l2h3, ob2, ob3, 1, TT - 1, o2, o3);
    }
}

extern "C" void kernel_launch(void* const* d_in, const int* in_sizes, int n_in,
                              void* d_out, int out_size)
{
    const float* x     = (const float*)d_in[0];
    const float* W_ih1 = (const float*)d_in[1];
    const float* W_hh1 = (const float*)d_in[2];
    const float* b_ih1 = (const float*)d_in[3];
    const float* b_hh1 = (const float*)d_in[4];
    const float* W_ih2 = (const float*)d_in[5];
    const float* W_hh2 = (const float*)d_in[6];
    const float* b_ih2 = (const float*)d_in[7];
    const float* b_hh2 = (const float*)d_in[8];

    const int B = in_sizes[0] / TT;   // x is [B, T, 1]
    lstm2_kernel<<<B / 4, 64>>>(x, W_ih1, W_hh1, b_ih1, b_hh1,
                                W_ih2, W_hh2, b_ih2, b_hh2,
                                (float*)d_out);
}